// round 6
// baseline (speedup 1.0000x reference)
#include <cuda_runtime.h>
#include <cstdint>

#define IN_F   128
#define HID_F  128
#define OUT_F  64
#define MAX_N  100000
#define MAX_E  1600000

// ---------------- scratch (static device memory; no allocations) ----------------
__device__ float g_dinv  [MAX_N];
__device__ int   g_cnt   [MAX_N];
__device__ int   g_rowptr[MAX_N + 1];
__device__ int   g_pos   [MAX_N];
__device__ int2  g_ecol  [MAX_E];          // .x = src id, .y = coef (float bits)
__device__ int   g_bsum  [512];
__device__ float g_h0    [(size_t)MAX_N * HID_F];
__device__ float g_h2    [(size_t)MAX_N * OUT_F];
__device__ int   g_is64;

// ---------------- zero counts + edge-index dtype detection ----------------------
__global__ void init_zero_detect(const unsigned int* __restrict__ w, int n) {
    int i = blockIdx.x * blockDim.x + threadIdx.x;
    if (i < n) g_cnt[i] = 0;
    if (i == 0) {
        int is64 = 1;
        for (int j = 1; j < 64; j += 2)
            if (w[j] != 0u) is64 = 0;
        g_is64 = is64;
    }
}

__device__ __forceinline__ void load_edge(const void* ei, int E, int i, int is64,
                                          int& s, int& d) {
    if (is64) {
        s = (int)((const long long*)ei)[i];
        d = (int)((const long long*)ei)[(size_t)E + i];
    } else {
        s = ((const int*)ei)[i];
        d = ((const int*)ei)[(size_t)E + i];
    }
}

// ---------------- CSR scan chain ------------------------------------------------
__global__ void scan_block(int n) {
    __shared__ int sh[256];
    int tid = threadIdx.x;
    int i = blockIdx.x * 256 + tid;
    int v = (i < n) ? g_cnt[i] : 0;
    sh[tid] = v;
    __syncthreads();
#pragma unroll
    for (int off = 1; off < 256; off <<= 1) {
        int t = (tid >= off) ? sh[tid - off] : 0;
        __syncthreads();
        sh[tid] += t;
        __syncthreads();
    }
    if (i < n) g_rowptr[i] = sh[tid] - v;
    if (tid == 255) g_bsum[blockIdx.x] = sh[255];
}

// merged top-scan + add: block offset = sum of g_bsum[0..blockIdx)
__global__ void scan_add(int n, int E) {
    __shared__ int red[8];
    __shared__ int offsh;
    int tid = threadIdx.x;
    int v = 0;
    for (int j = tid; j < blockIdx.x; j += 256) v += g_bsum[j];
#pragma unroll
    for (int o = 16; o; o >>= 1) v += __shfl_down_sync(0xffffffffu, v, o);
    if ((tid & 31) == 0) red[tid >> 5] = v;
    __syncthreads();
    if (tid == 0) {
        int s = 0;
#pragma unroll
        for (int j = 0; j < 8; j++) s += red[j];
        offsh = s;
    }
    __syncthreads();
    int off = offsh;
    int i = blockIdx.x * 256 + tid;
    if (i < n) {
        int r = g_rowptr[i] + off;
        g_rowptr[i] = r;
        g_pos[i] = r;
        g_dinv[i] = rsqrtf((float)g_cnt[i] + 1.0f);
    }
    if (i == 0) g_rowptr[n] = E;
}

__global__ void fill_kernel(const void* __restrict__ ei, int E) {
    const int is64 = g_is64;
    int i = blockIdx.x * blockDim.x + threadIdx.x;
    if (i < E) {
        int s, d; load_edge(ei, E, i, is64, s, d);
        int idx = atomicAdd(&g_pos[d], 1);
        float coef = g_dinv[s] * g_dinv[d];
        g_ecol[idx] = make_int2(s, __float_as_int(coef));
    }
}

// ---------------- tf32 helpers ---------------------------------------------------
__device__ __forceinline__ unsigned f2tf32(float f) {
    unsigned u;
    asm("cvt.rna.tf32.f32 %0, %1;" : "=r"(u) : "f"(f));
    return u;
}

// ---------------- TF32 GEMM (layer 1, with fused degree count) -------------------
// C[M,NC] = A[M,K] @ W[K,NC], fp32 accumulate. 64-row tiles,
// 8 warps = 2 m-groups (2 m-subtiles each) x 4 n-groups.
template<int K, int NC>
__global__ void __launch_bounds__(256) gemm_tc(
        const float* __restrict__ A, const float* __restrict__ W,
        float* __restrict__ C, int M,
        const void* __restrict__ ei, int E) {
    constexpr int KP   = K + 4;
    constexpr int NCP  = NC + 8;
    constexpr int NT_W = NC / 32;
    constexpr int K4   = K / 4;

    extern __shared__ unsigned sh[];
    unsigned* Ws = sh;                 // K * NCP
    unsigned* As = sh + K * NCP;       // 64 * KP

    const int tid = threadIdx.x;

    for (int i = tid; i < K * NC / 4; i += 256) {
        int k = i / (NC / 4), n4 = i - k * (NC / 4);
        float4 v = ((const float4*)W)[i];
        uint4 u = {f2tf32(v.x), f2tf32(v.y), f2tf32(v.z), f2tf32(v.w)};
        *(uint4*)(Ws + k * NCP + n4 * 4) = u;
    }

    // fused degree count (hidden behind GEMM traffic)
    {
        const int is64 = g_is64;
        for (int i = blockIdx.x * 256 + tid; i < E; i += gridDim.x * 256) {
            int d = is64 ? (int)((const long long*)ei)[(size_t)E + i]
                         : ((const int*)ei)[(size_t)E + i];
            atomicAdd(&g_cnt[d], 1);
        }
    }

    const int warp = tid >> 5, lane = tid & 31;
    const int g = lane >> 2, tg = lane & 3;
    const int mi = warp >> 2;
    const int ni = warp & 3;
    const int ntiles = (M + 63) >> 6;

    for (int tile = blockIdx.x; tile < ntiles; tile += gridDim.x) {
        const int row0 = tile << 6;
        __syncthreads();
        for (int i = tid; i < 64 * K4; i += 256) {
            int r = i / K4, c4 = i - r * K4;
            float4 v = {0.f, 0.f, 0.f, 0.f};
            if (row0 + r < M) v = *(const float4*)(A + (size_t)(row0 + r) * K + c4 * 4);
            uint4 u = {f2tf32(v.x), f2tf32(v.y), f2tf32(v.z), f2tf32(v.w)};
            *(uint4*)(As + r * KP + c4 * 4) = u;
        }
        __syncthreads();

        float acc[2][NT_W][4];
#pragma unroll
        for (int ms = 0; ms < 2; ms++)
#pragma unroll
            for (int t = 0; t < NT_W; t++)
#pragma unroll
                for (int v = 0; v < 4; v++) acc[ms][t][v] = 0.f;

        const unsigned* Arow0 = As + (mi * 32 + g) * KP;
        const unsigned* Arow1 = Arow0 + 16 * KP;
#pragma unroll
        for (int k0 = 0; k0 < K; k0 += 8) {
            unsigned a[2][4];
            a[0][0] = Arow0[k0 + tg];
            a[0][1] = Arow0[8 * KP + k0 + tg];
            a[0][2] = Arow0[k0 + tg + 4];
            a[0][3] = Arow0[8 * KP + k0 + tg + 4];
            a[1][0] = Arow1[k0 + tg];
            a[1][1] = Arow1[8 * KP + k0 + tg];
            a[1][2] = Arow1[k0 + tg + 4];
            a[1][3] = Arow1[8 * KP + k0 + tg + 4];
#pragma unroll
            for (int t = 0; t < NT_W; t++) {
                int n0 = ni * (NT_W * 8) + t * 8;
                unsigned b0 = Ws[(k0 + tg) * NCP + n0 + g];
                unsigned b1 = Ws[(k0 + tg + 4) * NCP + n0 + g];
#pragma unroll
                for (int ms = 0; ms < 2; ms++) {
                    asm volatile(
                        "mma.sync.aligned.m16n8k8.row.col.f32.tf32.tf32.f32 "
                        "{%0,%1,%2,%3},{%4,%5,%6,%7},{%8,%9},{%0,%1,%2,%3};\n"
                        : "+f"(acc[ms][t][0]), "+f"(acc[ms][t][1]),
                          "+f"(acc[ms][t][2]), "+f"(acc[ms][t][3])
                        : "r"(a[ms][0]), "r"(a[ms][1]), "r"(a[ms][2]), "r"(a[ms][3]),
                          "r"(b0), "r"(b1));
                }
            }
        }

#pragma unroll
        for (int ms = 0; ms < 2; ms++) {
            const int r0 = row0 + mi * 32 + ms * 16 + g;
            const int r1 = r0 + 8;
#pragma unroll
            for (int t = 0; t < NT_W; t++) {
                int n0 = ni * (NT_W * 8) + t * 8 + 2 * tg;
                if (r0 < M) {
                    float2 o = {acc[ms][t][0], acc[ms][t][1]};
                    *(float2*)(C + (size_t)r0 * NC + n0) = o;
                }
                if (r1 < M) {
                    float2 o = {acc[ms][t][2], acc[ms][t][3]};
                    *(float2*)(C + (size_t)r1 * NC + n0) = o;
                }
            }
        }
    }
}

// -------- fused CSR gather + TF32 GEMM -------------------------------------------
// For a 64-node tile: warp w gathers nodes [row0+8w, row0+8w+8): per node,
// acc = h[node]*dinv^2 + b_agg + sum_nbr h[s]*coef ; optional relu; optionally
// written to aggout (z); stored tf32 into smem A tile. Then MMA: C = A @ W (+bias).
template<int K, int NC, bool RELU, bool BIAS_OUT, bool WRITE_AGG>
__global__ void __launch_bounds__(256) fused_agg_gemm(
        const float* __restrict__ h, const float* __restrict__ b_agg,
        const float* __restrict__ W, const float* __restrict__ bias_out,
        float* __restrict__ C, float* __restrict__ aggout, int M) {
    constexpr int KP   = K + 4;
    constexpr int NCP  = NC + 8;
    constexpr int NT_W = NC / 32;
    constexpr int V    = K / 32;       // 4 (K=128) or 2 (K=64)

    extern __shared__ unsigned sh[];
    unsigned* Ws = sh;                 // K * NCP
    unsigned* As = sh + K * NCP;       // 64 * KP

    const int tid = threadIdx.x;
    for (int i = tid; i < K * NC / 4; i += 256) {
        int k = i / (NC / 4), n4 = i - k * (NC / 4);
        float4 v = ((const float4*)W)[i];
        uint4 u = {f2tf32(v.x), f2tf32(v.y), f2tf32(v.z), f2tf32(v.w)};
        *(uint4*)(Ws + k * NCP + n4 * 4) = u;
    }

    const int warp = tid >> 5, lane = tid & 31;
    const int g = lane >> 2, tg = lane & 3;
    const int mi = warp >> 2;
    const int ni = warp & 3;
    const int ntiles = (M + 63) >> 6;

    for (int tile = blockIdx.x; tile < ntiles; tile += gridDim.x) {
        const int row0 = tile << 6;
        __syncthreads();               // prior MMA reads of As done / Ws visible

        // ---- gather phase: 8 nodes per warp ----
        for (int r = 0; r < 8; r++) {
            const int node = row0 + warp * 8 + r;
            float acc[V];
            if (node < M) {
                float dv = g_dinv[node];
                float d2 = dv * dv;
                if (V == 4) {
                    float4 hv = ((const float4*)(h + (size_t)node * K))[lane];
                    float4 bv = ((const float4*)b_agg)[lane];
                    acc[0] = fmaf(hv.x, d2, bv.x); acc[1] = fmaf(hv.y, d2, bv.y);
                    acc[2] = fmaf(hv.z, d2, bv.z); acc[3] = fmaf(hv.w, d2, bv.w);
                } else {
                    float2 hv = ((const float2*)(h + (size_t)node * K))[lane];
                    float2 bv = ((const float2*)b_agg)[lane];
                    acc[0] = fmaf(hv.x, d2, bv.x); acc[1] = fmaf(hv.y, d2, bv.y);
                }
                const int beg = g_rowptr[node], end = g_rowptr[node + 1];
#pragma unroll 4
                for (int j = beg; j < end; j++) {
                    int2 e = g_ecol[j];                 // warp-uniform broadcast
                    float coef = __int_as_float(e.y);
                    if (V == 4) {
                        float4 v = ((const float4*)(h + (size_t)e.x * K))[lane];
                        acc[0] = fmaf(v.x, coef, acc[0]); acc[1] = fmaf(v.y, coef, acc[1]);
                        acc[2] = fmaf(v.z, coef, acc[2]); acc[3] = fmaf(v.w, coef, acc[3]);
                    } else {
                        float2 v = ((const float2*)(h + (size_t)e.x * K))[lane];
                        acc[0] = fmaf(v.x, coef, acc[0]); acc[1] = fmaf(v.y, coef, acc[1]);
                    }
                }
                if (RELU) {
#pragma unroll
                    for (int v = 0; v < V; v++) acc[v] = fmaxf(acc[v], 0.f);
                }
                if (WRITE_AGG) {
                    float* op = aggout + (size_t)node * K + lane * V;
                    if (V == 4) { float4 o = {acc[0], acc[1], acc[2], acc[3]}; *(float4*)op = o; }
                    else        { float2 o = {acc[0], acc[1]};                 *(float2*)op = o; }
                }
            } else {
#pragma unroll
                for (int v = 0; v < V; v++) acc[v] = 0.f;
            }
            unsigned* dst = As + (warp * 8 + r) * KP + lane * V;
            if (V == 4) {
                uint4 u = {f2tf32(acc[0]), f2tf32(acc[1]), f2tf32(acc[2]), f2tf32(acc[3])};
                *(uint4*)dst = u;
            } else {
                uint2 u = {f2tf32(acc[0]), f2tf32(acc[1])};
                *(uint2*)dst = u;
            }
        }
        __syncthreads();

        // ---- MMA phase ----
        float acc[2][NT_W][4];
#pragma unroll
        for (int ms = 0; ms < 2; ms++)
#pragma unroll
            for (int t = 0; t < NT_W; t++)
#pragma unroll
                for (int v = 0; v < 4; v++) acc[ms][t][v] = 0.f;

        const unsigned* Arow0 = As + (mi * 32 + g) * KP;
        const unsigned* Arow1 = Arow0 + 16 * KP;
#pragma unroll
        for (int k0 = 0; k0 < K; k0 += 8) {
            unsigned a[2][4];
            a[0][0] = Arow0[k0 + tg];
            a[0][1] = Arow0[8 * KP + k0 + tg];
            a[0][2] = Arow0[k0 + tg + 4];
            a[0][3] = Arow0[8 * KP + k0 + tg + 4];
            a[1][0] = Arow1[k0 + tg];
            a[1][1] = Arow1[8 * KP + k0 + tg];
            a[1][2] = Arow1[k0 + tg + 4];
            a[1][3] = Arow1[8 * KP + k0 + tg + 4];
#pragma unroll
            for (int t = 0; t < NT_W; t++) {
                int n0 = ni * (NT_W * 8) + t * 8;
                unsigned b0 = Ws[(k0 + tg) * NCP + n0 + g];
                unsigned b1 = Ws[(k0 + tg + 4) * NCP + n0 + g];
#pragma unroll
                for (int ms = 0; ms < 2; ms++) {
                    asm volatile(
                        "mma.sync.aligned.m16n8k8.row.col.f32.tf32.tf32.f32 "
                        "{%0,%1,%2,%3},{%4,%5,%6,%7},{%8,%9},{%0,%1,%2,%3};\n"
                        : "+f"(acc[ms][t][0]), "+f"(acc[ms][t][1]),
                          "+f"(acc[ms][t][2]), "+f"(acc[ms][t][3])
                        : "r"(a[ms][0]), "r"(a[ms][1]), "r"(a[ms][2]), "r"(a[ms][3]),
                          "r"(b0), "r"(b1));
                }
            }
        }

#pragma unroll
        for (int ms = 0; ms < 2; ms++) {
            const int r0 = row0 + mi * 32 + ms * 16 + g;
            const int r1 = r0 + 8;
#pragma unroll
            for (int t = 0; t < NT_W; t++) {
                int n0 = ni * (NT_W * 8) + t * 8 + 2 * tg;
                float bx = 0.f, by = 0.f;
                if (BIAS_OUT) { bx = bias_out[n0]; by = bias_out[n0 + 1]; }
                if (r0 < M) {
                    float2 o = {acc[ms][t][0] + bx, acc[ms][t][1] + by};
                    *(float2*)(C + (size_t)r0 * NC + n0) = o;
                }
                if (r1 < M) {
                    float2 o = {acc[ms][t][2] + bx, acc[ms][t][3] + by};
                    *(float2*)(C + (size_t)r1 * NC + n0) = o;
                }
            }
        }
    }
}

// --------------------------------- launch ---------------------------------------
extern "C" void kernel_launch(void* const* d_in, const int* in_sizes, int n_in,
                              void* d_out, int out_size) {
    const float* x  = (const float*)d_in[0];
    const void*  ei = d_in[1];
    const float* W1 = (const float*)d_in[2];
    const float* b1 = (const float*)d_in[3];
    const float* W2 = (const float*)d_in[4];
    const float* b2 = (const float*)d_in[5];
    const float* Wd = (const float*)d_in[6];
    const float* bd = (const float*)d_in[7];

    const int N = in_sizes[0] / IN_F;     // 100000
    const int E = in_sizes[1] / 2;        // 1.6M

    float* out = (float*)d_out;           // x_recon [N, IN_F]
    float* z   = out + (size_t)N * IN_F;  // z       [N, OUT_F]

    float *h0p, *h2p;
    cudaGetSymbolAddress((void**)&h0p, g_h0);
    cudaGetSymbolAddress((void**)&h2p, g_h2);

    // smem (bytes): Ws K*(NC+8) + As 64*(K+4)
    const int smem1 = (IN_F  * (HID_F + 8) + 64 * (IN_F  + 4)) * 4;  // 103424
    const int smem2 = (HID_F * (OUT_F + 8) + 64 * (HID_F + 4)) * 4;  //  70656
    const int smem3 = (OUT_F * (IN_F  + 8) + 64 * (OUT_F + 4)) * 4;  //  52224
    cudaFuncSetAttribute(gemm_tc<IN_F, HID_F>,
                         cudaFuncAttributeMaxDynamicSharedMemorySize, smem1);
    cudaFuncSetAttribute(fused_agg_gemm<HID_F, OUT_F, true, false, false>,
                         cudaFuncAttributeMaxDynamicSharedMemorySize, smem2);
    cudaFuncSetAttribute(fused_agg_gemm<OUT_F, IN_F, false, true, true>,
                         cudaFuncAttributeMaxDynamicSharedMemorySize, smem3);

    const int T = 256;
    const int nScanBlocks = (N + 255) / 256;

    // zero counts + dtype detect
    init_zero_detect<<<nScanBlocks, 256>>>((const unsigned int*)ei, N);

    // layer-1 GEMM with fused degree count: h0 = x @ W1
    gemm_tc<IN_F, HID_F><<<296, T, smem1>>>(x, W1, h0p, N, ei, E);

    // CSR: block scan -> merged top+add (also dinv) -> fill (per-edge coef)
    scan_block<<<nScanBlocks, 256>>>(N);
    scan_add<<<nScanBlocks, 256>>>(N, E);
    fill_kernel<<<(E + T - 1) / T, T>>>(ei, E);

    // fused: h2 = relu(gather(h0) + b1) @ W2
    fused_agg_gemm<HID_F, OUT_F, true, false, false><<<444, T, smem2>>>(
        h0p, b1, W2, nullptr, h2p, nullptr, N);

    // fused: z = gather(h2) + b2 (written to out) ; x_recon = z @ Wd + bd
    fused_agg_gemm<OUT_F, IN_F, false, true, true><<<592, T, smem3>>>(
        h2p, b2, Wd, bd, out, z, N);
}

// round 7
// speedup vs baseline: 1.8517x; 1.8517x over previous
#include <cuda_runtime.h>
#include <cuda_fp16.h>
#include <cstdint>

#define IN_F   128
#define HID_F  128
#define OUT_F  64
#define MAX_N  100000
#define MAX_E  1600000

// ---------------- scratch (static device memory; no allocations) ----------------
__device__ float  g_dinv  [MAX_N];
__device__ int    g_cnt   [MAX_N];
__device__ int    g_rowptr[MAX_N + 1];
__device__ int    g_pos   [MAX_N];
__device__ int2   g_ecol  [MAX_E];         // .x = src id, .y = coef (float bits)
__device__ int    g_bsum  [512];
__device__ __half g_h0h   [(size_t)MAX_N * HID_F];   // x @ W1            (fp16)
__device__ __half g_aggh  [(size_t)MAX_N * HID_F];   // relu(conv1 out)   (fp16)
__device__ __half g_h2h   [(size_t)MAX_N * OUT_F];   // h @ W2            (fp16)
__device__ int    g_is64;

// ---------------- zero counts + edge-index dtype detection ----------------------
__global__ void init_zero_detect(const unsigned int* __restrict__ w, int n) {
    int i = blockIdx.x * blockDim.x + threadIdx.x;
    if (i < n) g_cnt[i] = 0;
    if (i == 0) {
        int is64 = 1;
        for (int j = 1; j < 64; j += 2)
            if (w[j] != 0u) is64 = 0;
        g_is64 = is64;
    }
}

__device__ __forceinline__ void load_edge(const void* ei, int E, int i, int is64,
                                          int& s, int& d) {
    if (is64) {
        s = (int)((const long long*)ei)[i];
        d = (int)((const long long*)ei)[(size_t)E + i];
    } else {
        s = ((const int*)ei)[i];
        d = ((const int*)ei)[(size_t)E + i];
    }
}

// ---------------- CSR scan chain ------------------------------------------------
__global__ void scan_block(int n) {
    __shared__ int sh[256];
    int tid = threadIdx.x;
    int i = blockIdx.x * 256 + tid;
    int v = (i < n) ? g_cnt[i] : 0;
    sh[tid] = v;
    __syncthreads();
#pragma unroll
    for (int off = 1; off < 256; off <<= 1) {
        int t = (tid >= off) ? sh[tid - off] : 0;
        __syncthreads();
        sh[tid] += t;
        __syncthreads();
    }
    if (i < n) g_rowptr[i] = sh[tid] - v;
    if (tid == 255) g_bsum[blockIdx.x] = sh[255];
}

// merged top-scan + add: block offset = sum of g_bsum[0..blockIdx)
__global__ void scan_add(int n, int E) {
    __shared__ int red[8];
    __shared__ int offsh;
    int tid = threadIdx.x;
    int v = 0;
    for (int j = tid; j < blockIdx.x; j += 256) v += g_bsum[j];
#pragma unroll
    for (int o = 16; o; o >>= 1) v += __shfl_down_sync(0xffffffffu, v, o);
    if ((tid & 31) == 0) red[tid >> 5] = v;
    __syncthreads();
    if (tid == 0) {
        int s = 0;
#pragma unroll
        for (int j = 0; j < 8; j++) s += red[j];
        offsh = s;
    }
    __syncthreads();
    int off = offsh;
    int i = blockIdx.x * 256 + tid;
    if (i < n) {
        int r = g_rowptr[i] + off;
        g_rowptr[i] = r;
        g_pos[i] = r;
        g_dinv[i] = rsqrtf((float)g_cnt[i] + 1.0f);
    }
    if (i == 0) g_rowptr[n] = E;
}

__global__ void fill_kernel(const void* __restrict__ ei, int E) {
    const int is64 = g_is64;
    int i = blockIdx.x * blockDim.x + threadIdx.x;
    if (i < E) {
        int s, d; load_edge(ei, E, i, is64, s, d);
        int idx = atomicAdd(&g_pos[d], 1);
        float coef = g_dinv[s] * g_dinv[d];
        g_ecol[idx] = make_int2(s, __float_as_int(coef));
    }
}

// ---------------- tf32 helper ----------------------------------------------------
__device__ __forceinline__ unsigned f2tf32(float f) {
    unsigned u;
    asm("cvt.rna.tf32.f32 %0, %1;" : "=r"(u) : "f"(f));
    return u;
}

// ---------------- TF32 tensor-core GEMM ------------------------------------------
// C[M,NC] = A[M,K] @ W[K,NC] (+bias), fp32 accumulate. 64-row tiles,
// 8 warps = 2 m-groups (2 m-subtiles each) x 4 n-groups; B-frags reused.
// A_HALF: A is fp16 (exact cvt to tf32). OUT_HALF: C written fp16.
// COUNT: fused degree-count prologue over edge dst (hidden behind GEMM traffic).
template<int K, int NC, bool A_HALF, bool OUT_HALF, bool BIAS, bool COUNT>
__global__ void __launch_bounds__(256) gemm_tc(
        const void* __restrict__ Av, const float* __restrict__ W,
        const float* __restrict__ bias, void* __restrict__ Cv, int M,
        const void* __restrict__ ei, int E) {
    constexpr int KP   = K + 4;
    constexpr int NCP  = NC + 8;
    constexpr int NT_W = NC / 32;

    extern __shared__ unsigned sh[];
    unsigned* Ws = sh;                 // K * NCP
    unsigned* As = sh + K * NCP;       // 64 * KP

    const int tid = threadIdx.x;

    for (int i = tid; i < K * NC / 4; i += 256) {
        int k = i / (NC / 4), n4 = i - k * (NC / 4);
        float4 v = ((const float4*)W)[i];
        uint4 u = {f2tf32(v.x), f2tf32(v.y), f2tf32(v.z), f2tf32(v.w)};
        *(uint4*)(Ws + k * NCP + n4 * 4) = u;
    }

    if (COUNT) {
        const int is64 = g_is64;
        for (int i = blockIdx.x * 256 + tid; i < E; i += gridDim.x * 256) {
            int d = is64 ? (int)((const long long*)ei)[(size_t)E + i]
                         : ((const int*)ei)[(size_t)E + i];
            atomicAdd(&g_cnt[d], 1);
        }
    }

    const int warp = tid >> 5, lane = tid & 31;
    const int g = lane >> 2, tg = lane & 3;
    const int mi = warp >> 2;
    const int ni = warp & 3;
    const int ntiles = (M + 63) >> 6;

    for (int tile = blockIdx.x; tile < ntiles; tile += gridDim.x) {
        const int row0 = tile << 6;
        __syncthreads();
        // ---- stage 64-row A tile ----
        if (A_HALF) {
            const __half* A = (const __half*)Av;
            constexpr int K8 = K / 8;
            for (int i = tid; i < 64 * K8; i += 256) {
                int r = i / K8, c8 = i - r * K8;
                float f[8];
                if (row0 + r < M) {
                    uint4 u = *(const uint4*)(A + (size_t)(row0 + r) * K + c8 * 8);
                    const __half2* hp = (const __half2*)&u;
#pragma unroll
                    for (int q = 0; q < 4; q++) {
                        float2 f2 = __half22float2(hp[q]);
                        f[2 * q] = f2.x; f[2 * q + 1] = f2.y;
                    }
                } else {
#pragma unroll
                    for (int q = 0; q < 8; q++) f[q] = 0.f;
                }
                unsigned* dst = As + r * KP + c8 * 8;
                uint4 u0 = {f2tf32(f[0]), f2tf32(f[1]), f2tf32(f[2]), f2tf32(f[3])};
                uint4 u1 = {f2tf32(f[4]), f2tf32(f[5]), f2tf32(f[6]), f2tf32(f[7])};
                *(uint4*)dst = u0;
                *(uint4*)(dst + 4) = u1;
            }
        } else {
            const float* A = (const float*)Av;
            constexpr int K4 = K / 4;
            for (int i = tid; i < 64 * K4; i += 256) {
                int r = i / K4, c4 = i - r * K4;
                float4 v = {0.f, 0.f, 0.f, 0.f};
                if (row0 + r < M) v = *(const float4*)(A + (size_t)(row0 + r) * K + c4 * 4);
                uint4 u = {f2tf32(v.x), f2tf32(v.y), f2tf32(v.z), f2tf32(v.w)};
                *(uint4*)(As + r * KP + c4 * 4) = u;
            }
        }
        __syncthreads();

        float acc[2][NT_W][4];
#pragma unroll
        for (int ms = 0; ms < 2; ms++)
#pragma unroll
            for (int t = 0; t < NT_W; t++)
#pragma unroll
                for (int v = 0; v < 4; v++) acc[ms][t][v] = 0.f;

        const unsigned* Arow0 = As + (mi * 32 + g) * KP;
        const unsigned* Arow1 = Arow0 + 16 * KP;
#pragma unroll
        for (int k0 = 0; k0 < K; k0 += 8) {
            unsigned a[2][4];
            a[0][0] = Arow0[k0 + tg];
            a[0][1] = Arow0[8 * KP + k0 + tg];
            a[0][2] = Arow0[k0 + tg + 4];
            a[0][3] = Arow0[8 * KP + k0 + tg + 4];
            a[1][0] = Arow1[k0 + tg];
            a[1][1] = Arow1[8 * KP + k0 + tg];
            a[1][2] = Arow1[k0 + tg + 4];
            a[1][3] = Arow1[8 * KP + k0 + tg + 4];
#pragma unroll
            for (int t = 0; t < NT_W; t++) {
                int n0 = ni * (NT_W * 8) + t * 8;
                unsigned b0 = Ws[(k0 + tg) * NCP + n0 + g];
                unsigned b1 = Ws[(k0 + tg + 4) * NCP + n0 + g];
#pragma unroll
                for (int ms = 0; ms < 2; ms++) {
                    asm volatile(
                        "mma.sync.aligned.m16n8k8.row.col.f32.tf32.tf32.f32 "
                        "{%0,%1,%2,%3},{%4,%5,%6,%7},{%8,%9},{%0,%1,%2,%3};\n"
                        : "+f"(acc[ms][t][0]), "+f"(acc[ms][t][1]),
                          "+f"(acc[ms][t][2]), "+f"(acc[ms][t][3])
                        : "r"(a[ms][0]), "r"(a[ms][1]), "r"(a[ms][2]), "r"(a[ms][3]),
                          "r"(b0), "r"(b1));
                }
            }
        }

#pragma unroll
        for (int ms = 0; ms < 2; ms++) {
            const int r0 = row0 + mi * 32 + ms * 16 + g;
            const int r1 = r0 + 8;
#pragma unroll
            for (int t = 0; t < NT_W; t++) {
                int n0 = ni * (NT_W * 8) + t * 8 + 2 * tg;
                float bx = 0.f, by = 0.f;
                if (BIAS) { bx = bias[n0]; by = bias[n0 + 1]; }
                if (OUT_HALF) {
                    __half* C = (__half*)Cv;
                    if (r0 < M)
                        *(__half2*)(C + (size_t)r0 * NC + n0) =
                            __floats2half2_rn(acc[ms][t][0] + bx, acc[ms][t][1] + by);
                    if (r1 < M)
                        *(__half2*)(C + (size_t)r1 * NC + n0) =
                            __floats2half2_rn(acc[ms][t][2] + bx, acc[ms][t][3] + by);
                } else {
                    float* C = (float*)Cv;
                    if (r0 < M) {
                        float2 o = {acc[ms][t][0] + bx, acc[ms][t][1] + by};
                        *(float2*)(C + (size_t)r0 * NC + n0) = o;
                    }
                    if (r1 < M) {
                        float2 o = {acc[ms][t][2] + bx, acc[ms][t][3] + by};
                        *(float2*)(C + (size_t)r1 * NC + n0) = o;
                    }
                }
            }
        }
    }
}

// ------------- CSR gather aggregation (warp per destination row, fp16 source) ---
// out[i] = sum_nbr h[s]*coef + h[i]*dinv^2 + bias ; optional relu;
// OUT_HALF: write fp16, else fp32.
template<int F, bool RELU, bool OUT_HALF>
__global__ void __launch_bounds__(256) gather_agg(
        const __half* __restrict__ h, const float* __restrict__ bias,
        void* __restrict__ out, int Nn) {
    int w = (blockIdx.x * 256 + threadIdx.x) >> 5;
    int lane = threadIdx.x & 31;
    if (w >= Nn) return;
    constexpr int V = F / 32;               // halves per lane: 4 or 2

    float dv = g_dinv[w];
    float d2 = dv * dv;
    float acc[V];

    // self-loop + bias
    {
        const __half* hp = h + (size_t)w * F + lane * V;
        if (V == 4) {
            uint2 u = *(const uint2*)hp;
            float2 f0 = __half22float2(*(const __half2*)&u.x);
            float2 f1 = __half22float2(*(const __half2*)&u.y);
            acc[0] = fmaf(f0.x, d2, bias[lane * 4 + 0]);
            acc[1] = fmaf(f0.y, d2, bias[lane * 4 + 1]);
            acc[2] = fmaf(f1.x, d2, bias[lane * 4 + 2]);
            acc[3] = fmaf(f1.y, d2, bias[lane * 4 + 3]);
        } else {
            unsigned u = *(const unsigned*)hp;
            float2 f0 = __half22float2(*(const __half2*)&u);
            acc[0] = fmaf(f0.x, d2, bias[lane * 2 + 0]);
            acc[1] = fmaf(f0.y, d2, bias[lane * 2 + 1]);
        }
    }

    int beg = g_rowptr[w], end = g_rowptr[w + 1];
#pragma unroll 4
    for (int j = beg; j < end; j++) {
        int2 e = g_ecol[j];                 // warp-uniform broadcast load
        float coef = __int_as_float(e.y);
        const __half* hp = h + (size_t)e.x * F + lane * V;
        if (V == 4) {
            uint2 u = *(const uint2*)hp;
            float2 f0 = __half22float2(*(const __half2*)&u.x);
            float2 f1 = __half22float2(*(const __half2*)&u.y);
            acc[0] = fmaf(f0.x, coef, acc[0]); acc[1] = fmaf(f0.y, coef, acc[1]);
            acc[2] = fmaf(f1.x, coef, acc[2]); acc[3] = fmaf(f1.y, coef, acc[3]);
        } else {
            unsigned u = *(const unsigned*)hp;
            float2 f0 = __half22float2(*(const __half2*)&u);
            acc[0] = fmaf(f0.x, coef, acc[0]); acc[1] = fmaf(f0.y, coef, acc[1]);
        }
    }

    if (RELU) {
#pragma unroll
        for (int v = 0; v < V; v++) acc[v] = fmaxf(acc[v], 0.f);
    }

    if (OUT_HALF) {
        __half* op = (__half*)out + (size_t)w * F + lane * V;
        if (V == 4) {
            uint2 u;
            *(__half2*)&u.x = __floats2half2_rn(acc[0], acc[1]);
            *(__half2*)&u.y = __floats2half2_rn(acc[2], acc[3]);
            *(uint2*)op = u;
        } else {
            __half2 u = __floats2half2_rn(acc[0], acc[1]);
            *(__half2*)op = u;
        }
    } else {
        float* op = (float*)out + (size_t)w * F + lane * V;
        if (V == 4) { float4 o = {acc[0], acc[1], acc[2], acc[3]}; *(float4*)op = o; }
        else        { float2 o = {acc[0], acc[1]};                 *(float2*)op = o; }
    }
}

// --------------------------------- launch ---------------------------------------
extern "C" void kernel_launch(void* const* d_in, const int* in_sizes, int n_in,
                              void* d_out, int out_size) {
    const float* x  = (const float*)d_in[0];
    const void*  ei = d_in[1];
    const float* W1 = (const float*)d_in[2];
    const float* b1 = (const float*)d_in[3];
    const float* W2 = (const float*)d_in[4];
    const float* b2 = (const float*)d_in[5];
    const float* Wd = (const float*)d_in[6];
    const float* bd = (const float*)d_in[7];

    const int N = in_sizes[0] / IN_F;     // 100000
    const int E = in_sizes[1] / 2;        // 1.6M

    float* out = (float*)d_out;           // x_recon [N, IN_F]
    float* z   = out + (size_t)N * IN_F;  // z       [N, OUT_F]

    __half *h0p, *agghp, *h2p;
    cudaGetSymbolAddress((void**)&h0p,  g_h0h);
    cudaGetSymbolAddress((void**)&agghp, g_aggh);
    cudaGetSymbolAddress((void**)&h2p,  g_h2h);

    // smem (bytes): Ws K*(NC+8) + As 64*(K+4), 4B words
    const int smem1 = (IN_F  * (HID_F + 8) + 64 * (IN_F  + 4)) * 4;  // 103424
    const int smem2 = (HID_F * (OUT_F + 8) + 64 * (HID_F + 4)) * 4;  //  70656
    const int smem3 = (OUT_F * (IN_F  + 8) + 64 * (OUT_F + 4)) * 4;  //  52224
    cudaFuncSetAttribute(gemm_tc<IN_F, HID_F, false, true, false, true>,
                         cudaFuncAttributeMaxDynamicSharedMemorySize, smem1);
    cudaFuncSetAttribute(gemm_tc<HID_F, OUT_F, true, true, false, false>,
                         cudaFuncAttributeMaxDynamicSharedMemorySize, smem2);
    cudaFuncSetAttribute(gemm_tc<OUT_F, IN_F, false, false, true, false>,
                         cudaFuncAttributeMaxDynamicSharedMemorySize, smem3);

    const int T = 256;
    const int nScanBlocks = (N + 255) / 256;
    const int aggGrid = (N * 32 + T - 1) / T;     // warp per node

    // zero counts + dtype detect
    init_zero_detect<<<nScanBlocks, 256>>>((const unsigned int*)ei, N);

    // layer-1 GEMM (fp32 in, fp16 out) with fused degree count: h0 = x @ W1
    gemm_tc<IN_F, HID_F, false, true, false, true><<<296, T, smem1>>>(
        x, W1, nullptr, h0p, N, ei, E);

    // CSR: block scan -> merged top+add (also dinv) -> fill (per-edge coef)
    scan_block<<<nScanBlocks, 256>>>(N);
    scan_add<<<nScanBlocks, 256>>>(N, E);
    fill_kernel<<<(E + T - 1) / T, T>>>(ei, E);

    // layer-1 aggregation: aggh = relu(gather(h0) + b1)  (fp16)
    gather_agg<HID_F, true, true><<<aggGrid, T>>>(h0p, b1, agghp, N);

    // layer-2 GEMM (fp16 in, fp16 out): h2 = aggh @ W2
    gemm_tc<HID_F, OUT_F, true, true, false, false><<<444, T, smem2>>>(
        agghp, W2, nullptr, h2p, N, nullptr, 0);

    // layer-2 aggregation: z = gather(h2) + b2  (fp32, straight into d_out)
    gather_agg<OUT_F, false, false><<<aggGrid, T>>>(h2p, b2, z, N);

    // decoder (fp32 in from d_out, fp32 out): x_recon = z @ Wd + bd
    gemm_tc<OUT_F, IN_F, false, false, true, false><<<592, T, smem3>>>(
        z, Wd, bd, out, N, nullptr, 0);
}